// round 11
// baseline (speedup 1.0000x reference)
#include <cuda_runtime.h>
#include <cuda_fp16.h>
#include <math.h>
#include <stdint.h>

#define DD 768
#define G3 2304            // 3*DD
#define S_MAX 2048
#define E_MAX 32768
#define N_MAX 100000
#define R_MAX 1000

// ---------------- scratch (static __device__, no allocation) ----------------
__device__ float g_gi0[G3];
__device__ float g_sub[(size_t)S_MAX * DD];        // fp32 sub (k_r0 h-term, k_final)
__device__ float g_objw[(size_t)E_MAX * DD];
__device__ int   g_best[N_MAX];                    // 0 = unwritten, else timestamp+1
__device__ int   g_seedpos[N_MAX];
__device__ int   g_winedge[E_MAX];
__device__ int   g_winofnode[N_MAX];
__device__ int   g_wcount;

// fp16 arrays
__device__ __half h_bufG[(size_t)S_MAX * G3];      // gh0 then giH (fp16)
__device__ __half h_ghR [(size_t)R_MAX * G3];
__device__ __half h_smask[(size_t)S_MAX * DD];
__device__ __half h_subh [(size_t)S_MAX * DD];
__device__ __half h_r0h  [(size_t)S_MAX * DD];
__device__ __half h_relh [(size_t)R_MAX * DD];
__device__ __half h_rjwh [(size_t)E_MAX * DD];
__device__ __half h_Wsub[(size_t)DD * DD];
__device__ __half h_Whh [(size_t)G3 * DD];
__device__ __half h_Wih [(size_t)G3 * DD];
__device__ __half h_Wobj[(size_t)DD * DD];

// ---------------- helpers ----------------
__device__ __forceinline__ float fast_tanh(float x) {
    float y; asm("tanh.approx.f32 %0, %1;" : "=f"(y) : "f"(x)); return y;
}
__device__ __forceinline__ float fast_sigmoid(float x) {
    return 1.0f / (1.0f + __expf(-x));
}
__device__ __forceinline__ uint32_t smem_u32(const void* p) {
    uint32_t a;
    asm("{ .reg .u64 t; cvta.to.shared.u64 t, %1; cvt.u32.u64 %0, t; }" : "=r"(a) : "l"(p));
    return a;
}
#define SWZ128(o) ((o) ^ (((o) >> 3) & 0x70))

__device__ __forceinline__ void ldsm4(uint32_t addr, uint32_t* r) {
    asm volatile("ldmatrix.sync.aligned.m8n8.x4.shared.b16 {%0,%1,%2,%3}, [%4];"
                 : "=r"(r[0]), "=r"(r[1]), "=r"(r[2]), "=r"(r[3]) : "r"(addr));
}
__device__ __forceinline__ void mma_fp16(float* c, const uint32_t* a, const uint32_t* b) {
    asm volatile(
        "mma.sync.aligned.m16n8k16.row.col.f32.f16.f16.f32 "
        "{%0,%1,%2,%3}, {%4,%5,%6,%7}, {%8,%9}, {%0,%1,%2,%3};"
        : "+f"(c[0]), "+f"(c[1]), "+f"(c[2]), "+f"(c[3])
        : "r"(a[0]), "r"(a[1]), "r"(a[2]), "r"(a[3]), "r"(b[0]), "r"(b[1]));
}
__device__ __forceinline__ void cp16(uint32_t saddr, const void* g) {
    asm volatile("cp.async.cg.shared.global [%0], [%1], 16;" :: "r"(saddr), "l"(g));
}
__device__ __forceinline__ void cp_commit() {
    asm volatile("cp.async.commit_group;" ::: "memory");
}
template<int NN>
__device__ __forceinline__ void cp_wait() {
    asm volatile("cp.async.wait_group %0;" :: "n"(NN) : "memory");
}

// ---------------- small kernels ----------------
__global__ void k_seed(const int* __restrict__ seeds, int S, int stride) {
    int s = blockIdx.x * blockDim.x + threadIdx.x;
    if (s >= S) return;
    int node = seeds[s];
    g_seedpos[node] = s;
    atomicMax(&g_best[node], s * stride + 1);
}

__global__ void k_edget(const int* __restrict__ heads, const int* __restrict__ tails,
                        int E, int stride) {
    int e = blockIdx.x * blockDim.x + threadIdx.x;
    if (e >= E) return;
    int pos = g_seedpos[heads[e]];
    int t = pos * stride + 2 + e;
    atomicMax(&g_best[tails[e]], t);
}

// merged prepass: blocks [0, GI0_BLK) do gi0 (enc @ W_ih^T + b_ih, warp/output);
// remaining blocks do fp32->fp16 conversion for 6 tensors (grid-stride).
#define GI0_BLK 288
struct CvtJob { const float* src; __half* dst; int n4; };
__global__ void k_prep(const float* __restrict__ enc, const float* __restrict__ W_ih,
                       const float* __restrict__ b_ih,
                       CvtJob j0, CvtJob j1, CvtJob j2, CvtJob j3, CvtJob j4, CvtJob j5,
                       int total4) {
    if (blockIdx.x < GI0_BLK) {
        int warp = (blockIdx.x * blockDim.x + threadIdx.x) >> 5;
        int lane = threadIdx.x & 31;
        if (warp >= G3) return;
        const float* w = W_ih + (size_t)warp * DD;
        float s = 0.f;
        #pragma unroll 4
        for (int k = lane; k < DD; k += 32) s += enc[k] * w[k];
        #pragma unroll
        for (int off = 16; off; off >>= 1) s += __shfl_down_sync(0xffffffffu, s, off);
        if (lane == 0) g_gi0[warp] = s + b_ih[warp];
        return;
    }
    int nblk = gridDim.x - GI0_BLK;
    for (int i = (blockIdx.x - GI0_BLK) * blockDim.x + threadIdx.x; i < total4;
         i += nblk * blockDim.x) {
        int r = i;
        const float* s; __half* d;
        if (r < j0.n4)      { s = j0.src; d = j0.dst; }
        else { r -= j0.n4;
        if (r < j1.n4)      { s = j1.src; d = j1.dst; }
        else { r -= j1.n4;
        if (r < j2.n4)      { s = j2.src; d = j2.dst; }
        else { r -= j2.n4;
        if (r < j3.n4)      { s = j3.src; d = j3.dst; }
        else { r -= j3.n4;
        if (r < j4.n4)      { s = j4.src; d = j4.dst; }
        else { r -= j4.n4;    s = j5.src; d = j5.dst; } } } } }
        float4 v = ((const float4*)s)[r];
        ((__half2*)d)[2 * r]     = __halves2half2(__float2half(v.x), __float2half(v.y));
        ((__half2*)d)[2 * r + 1] = __halves2half2(__float2half(v.z), __float2half(v.w));
    }
}

// ---------------- fp16 HMMA GEMM (BK=64, SW128, 3-stage cp.async, 2 CTAs/SM) ----
#define BK     64
#define TILEB  (128 * 128)       // 16384 B (128 rows x 128 B)
#define STAGEB (2 * TILEB)       // 32768 B
#define NSTG   3
#define SMEM_DYN (NSTG * STAGEB) // 98304 B

template<int EPI, int OMODE>
__global__ void __launch_bounds__(256, 2)
k_hgemm(const __half* A, const __half* A2, const __half* __restrict__ Bw,
        const float* __restrict__ bias,
        float* __restrict__ C, __half* Ch, __half* Ch2,
        int M, int N, int K, int Ms, const int* __restrict__ mcount) {
    if (mcount) { int mc = *mcount; if (mc < M) M = mc; }
    int m0 = blockIdx.y * 128;
    int n0 = blockIdx.x * 128;
    if (m0 >= M) return;
    if (A2 && m0 >= Ms) {           // second segment (Ms is 128-aligned)
        A  = A2  - (size_t)Ms * K;
        Ch = Ch2 - (size_t)Ms * N;
    }

    extern __shared__ __align__(1024) char sm[];
    uint32_t smb = smem_u32(sm);

    int tid = threadIdx.x, lane = tid & 31, wid = tid >> 5;
    int wm = wid >> 1, wn = wid & 1;
    int g = lane >> 3, lr = lane & 7;
    uint32_t xorm = (uint32_t)((lr & 7) << 4);

    // producer mapping: 4 16B chunks per thread per tile (1024 chunks/tile)
    uint32_t so[4];
    size_t aoff[4], boff[4];
    #pragma unroll
    for (int i = 0; i < 4; i++) {
        int q = tid * 4 + i;
        int row = q >> 3, seg = q & 7;
        so[i] = SWZ128((uint32_t)(row * 128 + seg * 16));
        aoff[i] = (size_t)min(m0 + row, M - 1) * K + seg * 8;
        boff[i] = (size_t)(n0 + row) * K + seg * 8;
    }

    const int NC = K / BK;   // 12 for K=768

    auto issue = [&](int c) {
        uint32_t st = smb + (uint32_t)(c % NSTG) * STAGEB;
        int kc = c * BK;
        #pragma unroll
        for (int i = 0; i < 4; i++) cp16(st + so[i], A + aoff[i] + kc);
        #pragma unroll
        for (int i = 0; i < 4; i++) cp16(st + TILEB + so[i], Bw + boff[i] + kc);
        cp_commit();
    };

    float acc[2][8][4];
    #pragma unroll
    for (int i = 0; i < 2; i++)
        #pragma unroll
        for (int j = 0; j < 8; j++)
            #pragma unroll
            for (int q = 0; q < 4; q++) acc[i][j][q] = 0.f;

    issue(0); issue(1);

    for (int c = 0; c < NC; c++) {
        if (c + 1 < NC) cp_wait<1>();
        else            cp_wait<0>();
        // single barrier: publishes stage c AND proves stage (c-1)%3 fully read.
        __syncthreads();
        if (c + 2 < NC) issue(c + 2);   // writes stage (c+2)%3 == (c-1)%3 — safe

        uint32_t stage = smb + (uint32_t)(c % NSTG) * STAGEB;
        #pragma unroll
        for (int ks = 0; ks < 4; ks++) {
            uint32_t kb = (uint32_t)(ks * 32);
            uint32_t ah[2][4], bb[4][4];
            #pragma unroll
            for (int mt = 0; mt < 2; mt++) {
                uint32_t off = (uint32_t)(wm * 32 + mt * 16 + (g & 1) * 8 + lr) * 128
                             + ((kb + (g >> 1) * 16) ^ xorm);
                ldsm4(stage + off, ah[mt]);
            }
            #pragma unroll
            for (int q = 0; q < 4; q++) {
                uint32_t off = (uint32_t)(wn * 64 + q * 16 + (g >> 1) * 8 + lr) * 128
                             + ((kb + (g & 1) * 16) ^ xorm);
                ldsm4(stage + TILEB + off, bb[q]);
            }
            #pragma unroll
            for (int mt = 0; mt < 2; mt++)
                #pragma unroll
                for (int q = 0; q < 4; q++) {
                    mma_fp16(acc[mt][2 * q],     ah[mt], bb[q]);
                    mma_fp16(acc[mt][2 * q + 1], ah[mt], bb[q] + 2);
                }
        }
    }

    // ---- epilogue ----
    int lane4 = lane >> 2, lane2 = (lane & 3) * 2;
    #pragma unroll
    for (int mt = 0; mt < 2; mt++) {
        int r0 = m0 + wm * 32 + mt * 16 + lane4;
        #pragma unroll
        for (int q = 0; q < 8; q++) {
            int col = n0 + wn * 64 + q * 8 + lane2;
            float b0 = bias[col], b1 = bias[col + 1];
            float v0 = acc[mt][q][0] + b0, v1 = acc[mt][q][1] + b1;
            float v2 = acc[mt][q][2] + b0, v3 = acc[mt][q][3] + b1;
            if (EPI == 1) {
                v0 = fast_tanh(v0); v1 = fast_tanh(v1);
                v2 = fast_tanh(v2); v3 = fast_tanh(v3);
            }
            if (r0 < M) {
                if (OMODE != 2)
                    *(float2*)(C + (size_t)r0 * N + col) = make_float2(v0, v1);
                if (OMODE >= 1)
                    *(__half2*)(Ch + (size_t)r0 * N + col) =
                        __halves2half2(__float2half(v0), __float2half(v1));
            }
            if (r0 + 8 < M) {
                if (OMODE != 2)
                    *(float2*)(C + (size_t)(r0 + 8) * N + col) = make_float2(v2, v3);
                if (OMODE >= 1)
                    *(__half2*)(Ch + (size_t)(r0 + 8) * N + col) =
                        __halves2half2(__float2half(v2), __float2half(v3));
            }
        }
    }
}

// r0 = GRU combine (fp16 gates, half2-vectorized) -> fp16
__global__ void k_r0(int S) {
    int s = blockIdx.x;
    if (s >= S) return;
    const __half2* gh = (const __half2*)(h_bufG + (size_t)s * G3);
    const float2*  hb = (const float2*)(g_sub  + (size_t)s * DD);
    const float2*  gi = (const float2*)g_gi0;
    __half2* rh = (__half2*)(h_r0h + (size_t)s * DD);
    const int H = DD / 2;
    for (int d = threadIdx.x; d < H; d += blockDim.x) {
        float2 i_r = gi[d], i_z = gi[H + d], i_n = gi[2 * H + d];
        float2 hr = __half22float2(gh[d]);
        float2 hz = __half22float2(gh[H + d]);
        float2 hn = __half22float2(gh[2 * H + d]);
        float2 hv = hb[d];
        float r0_ = fast_sigmoid(i_r.x + hr.x), r1_ = fast_sigmoid(i_r.y + hr.y);
        float z0 = fast_sigmoid(i_z.x + hz.x), z1 = fast_sigmoid(i_z.y + hz.y);
        float n0 = fast_tanh(i_n.x + r0_ * hn.x), n1 = fast_tanh(i_n.y + r1_ * hn.y);
        rh[d] = __halves2half2(__float2half((1.f - z0) * n0 + z0 * hv.x),
                               __float2half((1.f - z1) * n1 + z1 * hv.y));
    }
}

__global__ void k_compact(const int* __restrict__ heads, const int* __restrict__ tails,
                          int E, int stride) {
    int e = blockIdx.x * blockDim.x + threadIdx.x;
    if (e >= E) return;
    int pos = g_seedpos[heads[e]];
    int t = pos * stride + 2 + e;
    int tl = tails[e];
    if (g_best[tl] == t) {
        int w = atomicAdd(&g_wcount, 1);
        g_winedge[w] = e;
        g_winofnode[tl] = w;
    }
}

// rj rows for winners (fp16 gates, half2-vectorized) -> fp16
__global__ void k_rj(const int* __restrict__ heads, const int* __restrict__ types,
                     const float* __restrict__ rel) {
    int w = blockIdx.x;
    if (w >= g_wcount) return;
    int e = g_winedge[w];
    int head = heads[e];
    int typ  = types[e];
    const __half2* gi = (const __half2*)(h_bufG + (size_t)head * G3);
    const __half2* gh = (const __half2*)(h_ghR  + (size_t)typ  * G3);
    const float2*  hv = (const float2*)(rel     + (size_t)typ  * DD);
    __half2* rh = (__half2*)(h_rjwh + (size_t)w * DD);
    const int H = DD / 2;
    for (int d = threadIdx.x; d < H; d += blockDim.x) {
        float2 ir = __half22float2(gi[d]);
        float2 iz = __half22float2(gi[H + d]);
        float2 in_ = __half22float2(gi[2 * H + d]);
        float2 hr = __half22float2(gh[d]);
        float2 hz = __half22float2(gh[H + d]);
        float2 hn = __half22float2(gh[2 * H + d]);
        float2 h2 = hv[d];
        float r0_ = fast_sigmoid(ir.x + hr.x), r1_ = fast_sigmoid(ir.y + hr.y);
        float z0 = fast_sigmoid(iz.x + hz.x), z1 = fast_sigmoid(iz.y + hz.y);
        float n0 = fast_tanh(in_.x + r0_ * hn.x), n1 = fast_tanh(in_.y + r1_ * hn.y);
        rh[d] = __halves2half2(__float2half((1.f - z0) * n0 + z0 * h2.x),
                               __float2half((1.f - z1) * n1 + z1 * h2.y));
    }
}

__global__ void k_final(const int* __restrict__ n2n, const int* __restrict__ oldnd,
                        const float* __restrict__ defnd, float* __restrict__ out,
                        int N, int stride) {
    int node = blockIdx.x;
    if (node >= N) return;
    int id = n2n[oldnd[node]];
    int b  = g_best[id];
    const float4* src;
    if (b == 0) {
        src = (const float4*)(defnd + (size_t)node * DD);
    } else if ((b - 1) % stride == 0) {
        src = (const float4*)(g_sub + (size_t)((b - 1) / stride) * DD);
    } else {
        src = (const float4*)(g_objw + (size_t)g_winofnode[id] * DD);
    }
    float4* dst = (float4*)(out + (size_t)node * DD);
    dst[threadIdx.x] = src[threadIdx.x];
}

// ---------------- launch ----------------
extern "C" void kernel_launch(void* const* d_in, const int* in_sizes, int n_in,
                              void* d_out, int out_size) {
    const float* enc    = (const float*)d_in[0];
    const float* smask  = (const float*)d_in[1];
    const int*   seeds  = (const int*)  d_in[2];
    const int*   eheads = (const int*)  d_in[3];
    const int*   etails = (const int*)  d_in[4];
    const int*   etype  = (const int*)  d_in[5];
    const int*   n2n    = (const int*)  d_in[6];
    const int*   oldnd  = (const int*)  d_in[7];
    const float* relemb = (const float*)d_in[8];
    const float* W_sub  = (const float*)d_in[9];
    const float* b_sub  = (const float*)d_in[10];
    const float* W_obj  = (const float*)d_in[11];
    const float* b_obj  = (const float*)d_in[12];
    const float* W_ih   = (const float*)d_in[13];
    const float* W_hh   = (const float*)d_in[14];
    const float* b_ih   = (const float*)d_in[15];
    const float* b_hh   = (const float*)d_in[16];
    const float* defnd  = (const float*)d_in[17];
    float* out = (float*)d_out;

    int S = in_sizes[2];
    int E = in_sizes[3];
    int N = in_sizes[6];
    int R = in_sizes[8] / DD;
    int stride = E + 1;

    float *p_sub, *p_objw;
    int *p_wcount, *p_best, *p_seedpos;
    __half *p_bufG, *p_ghR, *p_smh, *p_subh, *p_r0h, *p_relh, *p_rjh;
    __half *p_wsub, *p_whh, *p_wih, *p_wobj;
    cudaGetSymbolAddress((void**)&p_sub,     g_sub);
    cudaGetSymbolAddress((void**)&p_objw,    g_objw);
    cudaGetSymbolAddress((void**)&p_wcount,  g_wcount);
    cudaGetSymbolAddress((void**)&p_best,    g_best);
    cudaGetSymbolAddress((void**)&p_seedpos, g_seedpos);
    cudaGetSymbolAddress((void**)&p_bufG,    h_bufG);
    cudaGetSymbolAddress((void**)&p_ghR,     h_ghR);
    cudaGetSymbolAddress((void**)&p_smh,     h_smask);
    cudaGetSymbolAddress((void**)&p_subh,    h_subh);
    cudaGetSymbolAddress((void**)&p_r0h,     h_r0h);
    cudaGetSymbolAddress((void**)&p_relh,    h_relh);
    cudaGetSymbolAddress((void**)&p_rjh,     h_rjwh);
    cudaGetSymbolAddress((void**)&p_wsub,    h_Wsub);
    cudaGetSymbolAddress((void**)&p_whh,     h_Whh);
    cudaGetSymbolAddress((void**)&p_wih,     h_Wih);
    cudaGetSymbolAddress((void**)&p_wobj,    h_Wobj);

    cudaFuncSetAttribute(k_hgemm<0,2>, cudaFuncAttributeMaxDynamicSharedMemorySize, SMEM_DYN);
    cudaFuncSetAttribute(k_hgemm<1,0>, cudaFuncAttributeMaxDynamicSharedMemorySize, SMEM_DYN);
    cudaFuncSetAttribute(k_hgemm<1,1>, cudaFuncAttributeMaxDynamicSharedMemorySize, SMEM_DYN);

    // init via memset (graph-capturable)
    cudaMemsetAsync(p_best, 0, (size_t)N * sizeof(int));
    cudaMemsetAsync(p_seedpos, 0xFF, (size_t)N * sizeof(int));
    cudaMemsetAsync(p_wcount, 0, sizeof(int));

    // merged prepass: gi0 + all conversions
    {
        CvtJob j0 = {W_sub,  p_wsub, DD * DD / 4};
        CvtJob j1 = {W_hh,   p_whh,  G3 * DD / 4};
        CvtJob j2 = {W_ih,   p_wih,  G3 * DD / 4};
        CvtJob j3 = {W_obj,  p_wobj, DD * DD / 4};
        CvtJob j4 = {smask,  p_smh,  S * DD / 4};
        CvtJob j5 = {relemb, p_relh, R * DD / 4};
        int total4 = j0.n4 + j1.n4 + j2.n4 + j3.n4 + j4.n4 + j5.n4;
        int cvtb = (total4 + 255) / 256;
        k_prep<<<GI0_BLK + cvtb, 256>>>(enc, W_ih, b_ih, j0, j1, j2, j3, j4, j5, total4);
    }
    // scatter chain
    k_seed<<<(S + 255) / 256, 256>>>(seeds, S, stride);
    k_edget<<<(E + 255) / 256, 256>>>(eheads, etails, E, stride);
    // sub = tanh(mask @ W_sub^T + b_sub)  [fp32 + fp16 dual]
    {
        dim3 g(DD / 128, (S + 127) / 128);
        k_hgemm<1,1><<<g, 256, SMEM_DYN>>>(p_smh, nullptr, p_wsub, b_sub,
                                           p_sub, p_subh, nullptr,
                                           S, DD, DD, 1 << 30, nullptr);
    }
    // merged: [sub; rel] @ W_hh^T + b_hh -> [bufG; ghR] (fp16)
    {
        int yb = S / 128 + (R + 127) / 128;
        dim3 g(G3 / 128, yb);
        k_hgemm<0,2><<<g, 256, SMEM_DYN>>>(p_subh, p_relh, p_whh, b_hh,
                                           nullptr, p_bufG, p_ghR,
                                           S + R, G3, DD, S, nullptr);
    }
    // r0 combine -> fp16
    k_r0<<<S, 192>>>(S);
    // giH = r0 @ W_ih^T + b_ih -> fp16 bufG
    {
        dim3 g(G3 / 128, (S + 127) / 128);
        k_hgemm<0,2><<<g, 256, SMEM_DYN>>>(p_r0h, nullptr, p_wih, b_ih,
                                           nullptr, p_bufG, nullptr,
                                           S, G3, DD, 1 << 30, nullptr);
    }
    // winner compaction
    k_compact<<<(E + 255) / 256, 256>>>(eheads, etails, E, stride);
    // rj rows for winners -> fp16
    k_rj<<<E, 192>>>(eheads, etype, relemb);
    // objw = tanh(rjw @ W_obj^T + b_obj), M clamped by wcount
    {
        dim3 g(DD / 128, (E + 127) / 128);
        k_hgemm<1,0><<<g, 256, SMEM_DYN>>>(p_rjh, nullptr, p_wobj, b_obj,
                                           p_objw, nullptr, nullptr,
                                           E, DD, DD, 1 << 30, p_wcount);
    }
    // final gather
    k_final<<<N, 192>>>(n2n, oldnd, defnd, out, N, stride);
}